// round 1
// baseline (speedup 1.0000x reference)
#include <cuda_runtime.h>
#include <math.h>

#define TT 256
#define HH 512
#define LN_EPS 1e-5f

// ---------------- scratch (device globals; no allocation) ----------------
__device__ float g_z [TT*HH];   // relu(h@U + a)
__device__ float g_u [TT*HH];   // h .* z
__device__ float g_s [TT*HH];   // z@W + b
__device__ float g_d [TT*HH];   // dL/ds per row (rank-1 factor of gradW)
__device__ float g_P [TT*HH];   // inclusive column prefix of h
__device__ float g_Q [TT*HH];   // d .* P
__device__ float g_R1[TT*HH];   // S @ d
__device__ float g_R2[TT*HH];   // S @ Q
__device__ float g_c [TT];      // row sums of h
__device__ float g_S [TT*TT];   // causal scores (z @ u^T + c), strict lower-tri

// ---------------- 32x32 tiled GEMM body (NN), 256 threads, 2x2 micro ----------------
// EPI: 0 = plain, 1 = relu(acc+bias) and write u = h*z, 2 = acc+bias
template<int EPI>
__device__ __forceinline__ void gemm_nn_body(
    const float* __restrict__ A, const float* __restrict__ B,
    const float* __restrict__ bias, float* __restrict__ C,
    int M, int N, int K,
    const float* __restrict__ h, float* __restrict__ u)
{
    __shared__ float As[32][33];
    __shared__ float Bs[32][33];
    const int tid = threadIdx.x;
    const int tx = tid & 15, ty = tid >> 4;
    const int row0 = blockIdx.y * 32, col0 = blockIdx.x * 32;
    float acc00 = 0.f, acc01 = 0.f, acc10 = 0.f, acc11 = 0.f;

    for (int k0 = 0; k0 < K; k0 += 32) {
        #pragma unroll
        for (int i = 0; i < 4; i++) {
            int idx = tid + i * 256;
            int r = idx >> 5, cc = idx & 31;
            As[r][cc] = A[(row0 + r) * K + (k0 + cc)];
            Bs[r][cc] = B[(k0 + r) * N + (col0 + cc)];
        }
        __syncthreads();
        #pragma unroll
        for (int kk = 0; kk < 32; kk++) {
            float a0 = As[ty][kk], a1 = As[ty + 16][kk];
            float b0 = Bs[kk][tx], b1 = Bs[kk][tx + 16];
            acc00 += a0 * b0; acc01 += a0 * b1;
            acc10 += a1 * b0; acc11 += a1 * b1;
        }
        __syncthreads();
    }

    float accs[2][2] = {{acc00, acc01}, {acc10, acc11}};
    #pragma unroll
    for (int r = 0; r < 2; r++) {
        #pragma unroll
        for (int c = 0; c < 2; c++) {
            int rr = row0 + ty + 16 * r;
            int cc = col0 + tx + 16 * c;
            float v = accs[r][c];
            if (EPI >= 1) v += bias[cc];
            if (EPI == 1) {
                v = fmaxf(v, 0.f);
                u[rr * N + cc] = h[rr * N + cc] * v;
            }
            C[rr * N + cc] = v;
        }
    }
}

__global__ void k_gemm_z(const float* __restrict__ h, const float* __restrict__ U,
                         const float* __restrict__ a) {
    gemm_nn_body<1>(h, U, a, g_z, TT, HH, HH, h, g_u);
}

__global__ void k_gemm_s(const float* __restrict__ W, const float* __restrict__ b) {
    gemm_nn_body<2>(g_z, W, b, g_s, TT, HH, HH, nullptr, nullptr);
}

// ---------------- causal scores: S[t,i] = z_t . u_i + c_i, i < t else 0 ----------------
__global__ void k_scores() {
    __shared__ float As[32][33];
    __shared__ float Bs[32][33];
    const int tid = threadIdx.x;
    const int tx = tid & 15, ty = tid >> 4;
    const int row0 = blockIdx.y * 32, col0 = blockIdx.x * 32;
    float acc00 = 0.f, acc01 = 0.f, acc10 = 0.f, acc11 = 0.f;

    for (int k0 = 0; k0 < HH; k0 += 32) {
        #pragma unroll
        for (int i = 0; i < 4; i++) {
            int idx = tid + i * 256;
            int r = idx >> 5, cc = idx & 31;
            As[r][cc] = g_z[(row0 + r) * HH + (k0 + cc)];
            // B^T load: Bs[k][n] = u[(col0+n)*HH + k0+k]; coalesced on k
            Bs[cc][r] = g_u[(col0 + r) * HH + (k0 + cc)];
        }
        __syncthreads();
        #pragma unroll
        for (int kk = 0; kk < 32; kk++) {
            float a0 = As[ty][kk], a1 = As[ty + 16][kk];
            float b0 = Bs[kk][tx], b1 = Bs[kk][tx + 16];
            acc00 += a0 * b0; acc01 += a0 * b1;
            acc10 += a1 * b0; acc11 += a1 * b1;
        }
        __syncthreads();
    }

    float accs[2][2] = {{acc00, acc01}, {acc10, acc11}};
    #pragma unroll
    for (int r = 0; r < 2; r++) {
        #pragma unroll
        for (int c = 0; c < 2; c++) {
            int t = row0 + ty + 16 * r;
            int i = col0 + tx + 16 * c;
            g_S[t * TT + i] = (i < t) ? (accs[r][c] + g_c[i]) : 0.f;
        }
    }
}

// ---------------- dual GEMM: R1 = S @ d, R2 = S @ Q ----------------
__global__ void k_dual() {
    __shared__ float As [32][33];
    __shared__ float B1s[32][33];
    __shared__ float B2s[32][33];
    const int tid = threadIdx.x;
    const int tx = tid & 15, ty = tid >> 4;
    const int row0 = blockIdx.y * 32, col0 = blockIdx.x * 32;
    float a00 = 0.f, a01 = 0.f, a10 = 0.f, a11 = 0.f;   // R1 accum
    float b00 = 0.f, b01 = 0.f, b10 = 0.f, b11 = 0.f;   // R2 accum

    for (int k0 = 0; k0 < TT; k0 += 32) {
        #pragma unroll
        for (int i = 0; i < 4; i++) {
            int idx = tid + i * 256;
            int r = idx >> 5, cc = idx & 31;
            As [r][cc] = g_S[(row0 + r) * TT + (k0 + cc)];
            B1s[r][cc] = g_d[(k0 + r) * HH + (col0 + cc)];
            B2s[r][cc] = g_Q[(k0 + r) * HH + (col0 + cc)];
        }
        __syncthreads();
        #pragma unroll
        for (int kk = 0; kk < 32; kk++) {
            float s0 = As[ty][kk], s1 = As[ty + 16][kk];
            float d0 = B1s[kk][tx], d1 = B1s[kk][tx + 16];
            float q0 = B2s[kk][tx], q1 = B2s[kk][tx + 16];
            a00 += s0 * d0; a01 += s0 * d1;
            a10 += s1 * d0; a11 += s1 * d1;
            b00 += s0 * q0; b01 += s0 * q1;
            b10 += s1 * q0; b11 += s1 * q1;
        }
        __syncthreads();
    }
    float r1[2][2] = {{a00, a01}, {a10, a11}};
    float r2[2][2] = {{b00, b01}, {b10, b11}};
    #pragma unroll
    for (int r = 0; r < 2; r++)
        #pragma unroll
        for (int c = 0; c < 2; c++) {
            int rr = row0 + ty + 16 * r;
            int cc = col0 + tx + 16 * c;
            g_R1[rr * HH + cc] = r1[r][c];
            g_R2[rr * HH + cc] = r2[r][c];
        }
}

// ---------------- block reductions (broadcast result to all threads) ----------------
__device__ __forceinline__ float brsum(float v, float* sh) {
    #pragma unroll
    for (int o = 16; o; o >>= 1) v += __shfl_xor_sync(0xffffffffu, v, o);
    if ((threadIdx.x & 31) == 0) sh[threadIdx.x >> 5] = v;
    __syncthreads();
    float r = sh[0] + sh[1] + sh[2] + sh[3] + sh[4] + sh[5] + sh[6] + sh[7];
    __syncthreads();
    return r;
}
__device__ __forceinline__ float brmax(float v, float* sh) {
    #pragma unroll
    for (int o = 16; o; o >>= 1) v = fmaxf(v, __shfl_xor_sync(0xffffffffu, v, o));
    if ((threadIdx.x & 31) == 0) sh[threadIdx.x >> 5] = v;
    __syncthreads();
    float r = fmaxf(fmaxf(fmaxf(sh[0], sh[1]), fmaxf(sh[2], sh[3])),
                    fmaxf(fmaxf(sh[4], sh[5]), fmaxf(sh[6], sh[7])));
    __syncthreads();
    return r;
}

// ---------------- row sums of h -> c ----------------
__global__ void k_rowsum(const float* __restrict__ h) {
    const int t = blockIdx.x;
    float v = h[t * HH + threadIdx.x] + h[t * HH + threadIdx.x + 256];
    #pragma unroll
    for (int o = 16; o; o >>= 1) v += __shfl_xor_sync(0xffffffffu, v, o);
    __shared__ float sh[8];
    if ((threadIdx.x & 31) == 0) sh[threadIdx.x >> 5] = v;
    __syncthreads();
    if (threadIdx.x == 0) {
        float s = 0.f;
        #pragma unroll
        for (int i = 0; i < 8; i++) s += sh[i];
        g_c[t] = s;
    }
}

// ---------------- per-row: LN -> softmax -> CE+LN backward -> d ----------------
__global__ void k_grad(const float* __restrict__ gamma, const float* __restrict__ beta,
                       const int* __restrict__ targets) {
    __shared__ float sh[8];
    const int t = blockIdx.x;
    const int tid = threadIdx.x;
    const int i0 = t * HH + tid, i1 = i0 + 256;

    float s0 = g_s[i0], s1 = g_s[i1];
    float mu = brsum(s0 + s1, sh) * (1.f / HH);
    float e0 = s0 - mu, e1 = s1 - mu;
    float var = brsum(e0 * e0 + e1 * e1, sh) * (1.f / HH);
    float sinv = rsqrtf(var + LN_EPS);
    float xh0 = e0 * sinv, xh1 = e1 * sinv;

    float ga0 = gamma[tid], ga1 = gamma[tid + 256];
    float y0 = xh0 * ga0 + beta[tid];
    float y1 = xh1 * ga1 + beta[tid + 256];

    float m = brmax(fmaxf(y0, y1), sh);
    float p0 = __expf(y0 - m), p1 = __expf(y1 - m);
    float Zs = brsum(p0 + p1, sh);
    float inv = 1.f / Zs;
    p0 *= inv; p1 *= inv;

    const int tgt = targets[t];
    float gg0 = ga0 * (p0 - (tid == tgt ? 1.f : 0.f));
    float gg1 = ga1 * (p1 - (tid + 256 == tgt ? 1.f : 0.f));

    float mg  = brsum(gg0 + gg1, sh) * (1.f / HH);
    float mgx = brsum(gg0 * xh0 + gg1 * xh1, sh) * (1.f / HH);

    g_d[i0] = sinv * (gg0 - mg - xh0 * mgx);
    g_d[i1] = sinv * (gg1 - mg - xh1 * mgx);
}

// ---------------- column-wise inclusive prefix of h; Q = d .* P ----------------
__global__ void k_prefix(const float* __restrict__ h) {
    const int q = blockIdx.x * 256 + threadIdx.x;   // 2 blocks x 256 = 512 cols
    float run = 0.f;
    for (int t = 0; t < TT; t++) {
        int idx = t * HH + q;
        run += h[idx];
        g_P[idx] = run;
        g_Q[idx] = g_d[idx] * run;
    }
}

// ---------------- final: pre = s - (P*R1 - R2); out = LN(pre)*gamma + beta ----------------
__global__ void k_final(const float* __restrict__ gamma, const float* __restrict__ beta,
                        float* __restrict__ out) {
    __shared__ float sh[8];
    const int t = blockIdx.x;
    const int tid = threadIdx.x;
    const int i0 = t * HH + tid, i1 = i0 + 256;

    float pre0 = g_s[i0] - (g_P[i0] * g_R1[i0] - g_R2[i0]);
    float pre1 = g_s[i1] - (g_P[i1] * g_R1[i1] - g_R2[i1]);

    float mu = brsum(pre0 + pre1, sh) * (1.f / HH);
    float e0 = pre0 - mu, e1 = pre1 - mu;
    float var = brsum(e0 * e0 + e1 * e1, sh) * (1.f / HH);
    float sinv = rsqrtf(var + LN_EPS);

    out[i0] = e0 * sinv * gamma[tid]       + beta[tid];
    out[i1] = e1 * sinv * gamma[tid + 256] + beta[tid + 256];
}

// ---------------- launch ----------------
extern "C" void kernel_launch(void* const* d_in, const int* in_sizes, int n_in,
                              void* d_out, int out_size) {
    const float* h      = (const float*)d_in[0];   // (1, 256, 512)
    const float* U      = (const float*)d_in[1];   // (512, 512)
    const float* W      = (const float*)d_in[2];   // (512, 512)
    const float* a      = (const float*)d_in[3];   // (512,)
    const float* b      = (const float*)d_in[4];   // (512,)
    const float* gamma  = (const float*)d_in[5];   // (512,)
    const float* beta   = (const float*)d_in[6];   // (512,)
    const int*   tgt    = (const int*)  d_in[7];   // (256,)
    float*       out    = (float*)d_out;           // (1, 256, 512)

    dim3 blk(256);
    dim3 gBig(HH / 32, TT / 32);   // 16 x 8 = 128 blocks
    dim3 gSco(TT / 32, TT / 32);   //  8 x 8 =  64 blocks

    k_gemm_z <<<gBig, blk>>>(h, U, a);          // z = relu(h@U+a), u = h.*z
    k_rowsum <<<TT,   blk>>>(h);                // c_t = sum_q h[t,q]
    k_gemm_s <<<gBig, blk>>>(W, b);             // s = z@W + b
    k_grad   <<<TT,   blk>>>(gamma, beta, tgt); // d = LN/CE backward per row
    k_prefix <<<2,    blk>>>(h);                // P = cumsum(h), Q = d.*P
    k_scores <<<gSco, blk>>>();                 // S = causal(z@u^T + c)
    k_dual   <<<gBig, blk>>>();                 // R1 = S@d, R2 = S@Q
    k_final  <<<TT,   blk>>>(gamma, beta, out); // out = LN(s - (P*R1 - R2))
}

// round 3
// speedup vs baseline: 2.2986x; 2.2986x over previous
#include <cuda_runtime.h>
#include <math.h>

#define TT 256
#define HH 512
#define LN_EPS 1e-5f

// ---------------- scratch (device globals; no allocation) ----------------
__device__ float g_z [TT*HH];   // relu(h@U + a)
__device__ float g_u [TT*HH];   // h .* z
__device__ float g_s [TT*HH];   // z@W + b
__device__ float g_d [TT*HH];   // dL/ds per row
__device__ float g_P [TT*HH];   // inclusive column prefix of h
__device__ float g_R1[TT*HH];   // S @ d
__device__ float g_R2[TT*HH];   // S @ (d.*P)
__device__ float g_c [TT];      // row sums of h
__device__ float g_S [TT*TT];   // causal scores

// =====================================================================
// 32x32 block-tiled GEMM, 256 threads, 2x2 micro, transposed-A smem,
// double-buffered. FMA-pipe bound: 2xLDS.64 + 4 FFMA per kk per thread.
// EPI: 1 = relu(acc+bias), also u = h.*z ; 2 = acc+bias
// =====================================================================
template<int EPI>
__device__ __forceinline__ void gemm32_body(
    const float* __restrict__ A, const float* __restrict__ B,
    const float* __restrict__ bias, float* __restrict__ C,
    int N, int K,
    const float* __restrict__ h, float* __restrict__ u)
{
    __shared__ __align__(16) float Ast[2][32][34];   // [buf][kk][row]
    __shared__ __align__(16) float Bs [2][32][34];   // [buf][kk][col]

    const int tid  = threadIdx.x;
    const int tx   = tid & 15;        // col-pair
    const int ty   = tid >> 4;        // row-pair
    const int r_ld = tid >> 5;        // 0..7
    const int c_ld = tid & 31;        // 0..31
    const int row0 = blockIdx.y * 32, col0 = blockIdx.x * 32;

    // preload tile 0
    #pragma unroll
    for (int i = 0; i < 4; i++) {
        int r = r_ld + i * 8;
        Ast[0][c_ld][r] = A[(row0 + r) * K + c_ld];
        Bs [0][r][c_ld] = B[r * N + col0 + c_ld];
    }
    __syncthreads();

    float acc00 = 0.f, acc01 = 0.f, acc10 = 0.f, acc11 = 0.f;
    float a_reg[4], b_reg[4];
    const int NT = K / 32;

    for (int t = 0; t < NT; t++) {
        const int buf = t & 1;
        if (t + 1 < NT) {
            const int k0 = (t + 1) * 32;
            #pragma unroll
            for (int i = 0; i < 4; i++) {
                int r = r_ld + i * 8;
                a_reg[i] = A[(row0 + r) * K + k0 + c_ld];
                b_reg[i] = B[(k0 + r) * N + col0 + c_ld];
            }
        }
        #pragma unroll
        for (int kk = 0; kk < 32; kk++) {
            float2 av = *(const float2*)&Ast[buf][kk][2 * ty];
            float2 bv = *(const float2*)&Bs [buf][kk][2 * tx];
            acc00 += av.x * bv.x; acc01 += av.x * bv.y;
            acc10 += av.y * bv.x; acc11 += av.y * bv.y;
        }
        if (t + 1 < NT) {
            #pragma unroll
            for (int i = 0; i < 4; i++) {
                int r = r_ld + i * 8;
                Ast[buf ^ 1][c_ld][r] = a_reg[i];
                Bs [buf ^ 1][r][c_ld] = b_reg[i];
            }
        }
        __syncthreads();
    }

    const int rr0 = row0 + 2 * ty;
    const int cc0 = col0 + 2 * tx;
    float accs[2][2] = {{acc00, acc01}, {acc10, acc11}};
    #pragma unroll
    for (int r = 0; r < 2; r++) {
        int rr = rr0 + r;
        float v0 = accs[r][0], v1 = accs[r][1];
        if (EPI >= 1) { v0 += bias[cc0]; v1 += bias[cc0 + 1]; }
        if (EPI == 1) {
            v0 = fmaxf(v0, 0.f); v1 = fmaxf(v1, 0.f);
            float2 hv = *(const float2*)&h[rr * HH + cc0];
            *(float2*)&u[rr * HH + cc0] = make_float2(hv.x * v0, hv.y * v1);
        }
        *(float2*)&C[rr * N + cc0] = make_float2(v0, v1);
    }
}

__global__ __launch_bounds__(256) void k_gemm_z(
    const float* __restrict__ h, const float* __restrict__ U,
    const float* __restrict__ a) {
    gemm32_body<1>(h, U, a, g_z, HH, HH, h, g_u);
}

__global__ __launch_bounds__(256) void k_gemm_s(
    const float* __restrict__ W, const float* __restrict__ b) {
    gemm32_body<2>(g_z, W, b, g_s, HH, HH, nullptr, nullptr);
}

// ---------------- causal scores: S[t,i] = z_t . u_i + c_i (i<t) ----------------
__global__ __launch_bounds__(256) void k_scores() {
    __shared__ __align__(16) float Ast[2][32][34];   // z^T tile
    __shared__ __align__(16) float Bs [2][32][34];   // u^T tile (i along 2nd idx)

    const int tid  = threadIdx.x;
    const int tx   = tid & 15;
    const int ty   = tid >> 4;
    const int r_ld = tid >> 5;
    const int c_ld = tid & 31;
    const int row0 = blockIdx.y * 32, col0 = blockIdx.x * 32;

    #pragma unroll
    for (int i = 0; i < 4; i++) {
        int r = r_ld + i * 8;
        Ast[0][c_ld][r] = g_z[(row0 + r) * HH + c_ld];
        Bs [0][c_ld][r] = g_u[(col0 + r) * HH + c_ld];
    }
    __syncthreads();

    float acc00 = 0.f, acc01 = 0.f, acc10 = 0.f, acc11 = 0.f;
    float a_reg[4], b_reg[4];
    const int NT = HH / 32;

    for (int t = 0; t < NT; t++) {
        const int buf = t & 1;
        if (t + 1 < NT) {
            const int k0 = (t + 1) * 32;
            #pragma unroll
            for (int i = 0; i < 4; i++) {
                int r = r_ld + i * 8;
                a_reg[i] = g_z[(row0 + r) * HH + k0 + c_ld];
                b_reg[i] = g_u[(col0 + r) * HH + k0 + c_ld];
            }
        }
        #pragma unroll
        for (int kk = 0; kk < 32; kk++) {
            float2 av = *(const float2*)&Ast[buf][kk][2 * ty];
            float2 bv = *(const float2*)&Bs [buf][kk][2 * tx];
            acc00 += av.x * bv.x; acc01 += av.x * bv.y;
            acc10 += av.y * bv.x; acc11 += av.y * bv.y;
        }
        if (t + 1 < NT) {
            #pragma unroll
            for (int i = 0; i < 4; i++) {
                int r = r_ld + i * 8;
                Ast[buf ^ 1][c_ld][r] = a_reg[i];
                Bs [buf ^ 1][c_ld][r] = b_reg[i];
            }
        }
        __syncthreads();
    }

    const int t0 = row0 + 2 * ty;
    const int i0 = col0 + 2 * tx;
    float accs[2][2] = {{acc00, acc01}, {acc10, acc11}};
    float ci0 = g_c[i0], ci1 = g_c[i0 + 1];
    #pragma unroll
    for (int r = 0; r < 2; r++) {
        int tt = t0 + r;
        float v0 = (i0     < tt) ? (accs[r][0] + ci0) : 0.f;
        float v1 = (i0 + 1 < tt) ? (accs[r][1] + ci1) : 0.f;
        *(float2*)&g_S[tt * TT + i0] = make_float2(v0, v1);
    }
}

// ---------------- dual GEMM: R1 = S@d, R2 = S@(d.*P) ----------------
__global__ __launch_bounds__(256) void k_dual() {
    __shared__ __align__(16) float Ast[2][32][34];
    __shared__ __align__(16) float B1s[2][32][34];
    __shared__ __align__(16) float B2s[2][32][34];

    const int tid  = threadIdx.x;
    const int tx   = tid & 15;
    const int ty   = tid >> 4;
    const int r_ld = tid >> 5;
    const int c_ld = tid & 31;
    const int row0 = blockIdx.y * 32, col0 = blockIdx.x * 32;

    #pragma unroll
    for (int i = 0; i < 4; i++) {
        int r = r_ld + i * 8;
        Ast[0][c_ld][r] = g_S[(row0 + r) * TT + c_ld];
        int bidx = r * HH + col0 + c_ld;
        float dv = g_d[bidx];
        B1s[0][r][c_ld] = dv;
        B2s[0][r][c_ld] = dv * g_P[bidx];
    }
    __syncthreads();

    float a00=0.f,a01=0.f,a10=0.f,a11=0.f;
    float b00=0.f,b01=0.f,b10=0.f,b11=0.f;
    float a_reg[4], d_reg[4], q_reg[4];
    const int NT = TT / 32;

    for (int t = 0; t < NT; t++) {
        const int buf = t & 1;
        if (t + 1 < NT) {
            const int k0 = (t + 1) * 32;
            #pragma unroll
            for (int i = 0; i < 4; i++) {
                int r = r_ld + i * 8;
                a_reg[i] = g_S[(row0 + r) * TT + k0 + c_ld];
                int bidx = (k0 + r) * HH + col0 + c_ld;
                float dv = g_d[bidx];
                d_reg[i] = dv;
                q_reg[i] = dv * g_P[bidx];
            }
        }
        #pragma unroll
        for (int kk = 0; kk < 32; kk++) {
            float2 sv = *(const float2*)&Ast[buf][kk][2 * ty];
            float2 dv = *(const float2*)&B1s[buf][kk][2 * tx];
            float2 qv = *(const float2*)&B2s[buf][kk][2 * tx];
            a00 += sv.x * dv.x; a01 += sv.x * dv.y;
            a10 += sv.y * dv.x; a11 += sv.y * dv.y;
            b00 += sv.x * qv.x; b01 += sv.x * qv.y;
            b10 += sv.y * qv.x; b11 += sv.y * qv.y;
        }
        if (t + 1 < NT) {
            #pragma unroll
            for (int i = 0; i < 4; i++) {
                int r = r_ld + i * 8;
                Ast[buf ^ 1][c_ld][r] = a_reg[i];
                B1s[buf ^ 1][r][c_ld] = d_reg[i];
                B2s[buf ^ 1][r][c_ld] = q_reg[i];
            }
        }
        __syncthreads();
    }

    const int rr0 = row0 + 2 * ty;
    const int cc0 = col0 + 2 * tx;
    float r1[2][2] = {{a00,a01},{a10,a11}};
    float r2[2][2] = {{b00,b01},{b10,b11}};
    #pragma unroll
    for (int r = 0; r < 2; r++) {
        int rr = rr0 + r;
        *(float2*)&g_R1[rr * HH + cc0] = make_float2(r1[r][0], r1[r][1]);
        *(float2*)&g_R2[rr * HH + cc0] = make_float2(r2[r][0], r2[r][1]);
    }
}

// ---------------- block reductions ----------------
__device__ __forceinline__ float2 brsum2(float a, float b, float2* sh) {
    #pragma unroll
    for (int o = 16; o; o >>= 1) {
        a += __shfl_xor_sync(0xffffffffu, a, o);
        b += __shfl_xor_sync(0xffffffffu, b, o);
    }
    if ((threadIdx.x & 31) == 0) sh[threadIdx.x >> 5] = make_float2(a, b);
    __syncthreads();
    float sa = 0.f, sb = 0.f;
    #pragma unroll
    for (int i = 0; i < 8; i++) { sa += sh[i].x; sb += sh[i].y; }
    __syncthreads();
    return make_float2(sa, sb);
}
__device__ __forceinline__ float brsum1(float a, float2* sh) {
    #pragma unroll
    for (int o = 16; o; o >>= 1) a += __shfl_xor_sync(0xffffffffu, a, o);
    if ((threadIdx.x & 31) == 0) sh[threadIdx.x >> 5].x = a;
    __syncthreads();
    float s = 0.f;
    #pragma unroll
    for (int i = 0; i < 8; i++) s += sh[i].x;
    __syncthreads();
    return s;
}

// ---------------- prep: P = colwise cumsum(h); c = rowwise sum(h) ----------------
__global__ __launch_bounds__(256) void k_prep(const float* __restrict__ h) {
    if (blockIdx.x < 2) {
        const int q = blockIdx.x * 256 + threadIdx.x;
        float run = 0.f;
        for (int t = 0; t < TT; t++) {
            int idx = t * HH + q;
            run += h[idx];
            g_P[idx] = run;
        }
    } else {
        const int warp = threadIdx.x >> 5, lane = threadIdx.x & 31;
        const int row = (blockIdx.x - 2) * 8 + warp;
        const float* hr = h + row * HH;
        float v = 0.f;
        #pragma unroll
        for (int j = 0; j < 16; j++) v += hr[lane + j * 32];
        #pragma unroll
        for (int o = 16; o; o >>= 1) v += __shfl_xor_sync(0xffffffffu, v, o);
        if (lane == 0) g_c[row] = v;
    }
}

// ---------------- per-row LN -> softmax -> CE+LN backward -> d ----------------
__global__ __launch_bounds__(256) void k_grad(
    const float* __restrict__ gamma, const float* __restrict__ beta,
    const int* __restrict__ targets) {
    __shared__ float2 sh[8];
    const int t = blockIdx.x;
    const int tid = threadIdx.x;
    const int i0 = t * HH + tid, i1 = i0 + 256;

    float s0 = g_s[i0], s1 = g_s[i1];
    float2 r = brsum2(s0 + s1, s0 * s0 + s1 * s1, sh);
    float mu = r.x * (1.f / HH);
    float var = r.y * (1.f / HH) - mu * mu;
    float sinv = rsqrtf(var + LN_EPS);
    float xh0 = (s0 - mu) * sinv, xh1 = (s1 - mu) * sinv;

    float ga0 = gamma[tid], ga1 = gamma[tid + 256];
    float y0 = xh0 * ga0 + beta[tid];
    float y1 = xh1 * ga1 + beta[tid + 256];

    // LN output is bounded (|xhat| <= sqrt(H)); exp without max-sub is safe in fp32
    float p0 = __expf(y0), p1 = __expf(y1);
    float Zs = brsum1(p0 + p1, sh);
    float inv = 1.f / Zs;
    p0 *= inv; p1 *= inv;

    const int tgt = targets[t];
    float gg0 = ga0 * (p0 - (tid == tgt ? 1.f : 0.f));
    float gg1 = ga1 * (p1 - (tid + 256 == tgt ? 1.f : 0.f));

    float2 m2 = brsum2(gg0 + gg1, gg0 * xh0 + gg1 * xh1, sh);
    float mg  = m2.x * (1.f / HH);
    float mgx = m2.y * (1.f / HH);

    g_d[i0] = sinv * (gg0 - mg - xh0 * mgx);
    g_d[i1] = sinv * (gg1 - mg - xh1 * mgx);
}

// ---------------- final: pre = s - (P*R1 - R2); out = LN(pre) ----------------
__global__ __launch_bounds__(256) void k_final(
    const float* __restrict__ gamma, const float* __restrict__ beta,
    float* __restrict__ out) {
    __shared__ float2 sh[8];
    const int t = blockIdx.x;
    const int tid = threadIdx.x;
    const int i0 = t * HH + tid, i1 = i0 + 256;

    float pre0 = g_s[i0] - (g_P[i0] * g_R1[i0] - g_R2[i0]);
    float pre1 = g_s[i1] - (g_P[i1] * g_R1[i1] - g_R2[i1]);

    float2 r = brsum2(pre0 + pre1, pre0 * pre0 + pre1 * pre1, sh);
    float mu = r.x * (1.f / HH);
    float var = r.y * (1.f / HH) - mu * mu;
    float sinv = rsqrtf(var + LN_EPS);

    out[i0] = (pre0 - mu) * sinv * gamma[tid]       + beta[tid];
    out[i1] = (pre1 - mu) * sinv * gamma[tid + 256] + beta[tid + 256];
}

// ---------------- launch ----------------
extern "C" void kernel_launch(void* const* d_in, const int* in_sizes, int n_in,
                              void* d_out, int out_size) {
    const float* h      = (const float*)d_in[0];
    const float* U      = (const float*)d_in[1];
    const float* W      = (const float*)d_in[2];
    const float* a      = (const float*)d_in[3];
    const float* b      = (const float*)d_in[4];
    const float* gamma  = (const float*)d_in[5];
    const float* beta   = (const float*)d_in[6];
    const int*   tgt    = (const int*)  d_in[7];
    float*       out    = (float*)d_out;

    dim3 blk(256);
    dim3 gBig(HH / 32, TT / 32);   // 16 x 8 = 128 blocks
    dim3 gSco(TT / 32, TT / 32);   //  8 x 8 =  64 blocks

    k_prep   <<<34,   blk>>>(h);                // P = cumsum(h), c = rowsum(h)
    k_gemm_z <<<gBig, blk>>>(h, U, a);          // z = relu(h@U+a), u = h.*z
    k_gemm_s <<<gBig, blk>>>(W, b);             // s = z@W + b
    k_scores <<<gSco, blk>>>();                 // S = causal(z@u^T + c)
    k_grad   <<<TT,   blk>>>(gamma, beta, tgt); // d = LN/CE backward per row
    k_dual   <<<gBig, blk>>>();                 // R1 = S@d, R2 = S@(d.*P)
    k_final  <<<TT,   blk>>>(gamma, beta, out); // out = LN(s - (P*R1 - R2))
}

// round 4
// speedup vs baseline: 2.8339x; 1.2328x over previous
#include <cuda_runtime.h>
#include <math.h>

#define TT 256
#define HH 512
#define LN_EPS 1e-5f
#define NSPLIT 4   // split-K for K=512 GEMMs
#define KSPL   128 // 512 / 4

// ---------------- scratch (device globals; no allocation) ----------------
__device__ float g_zp[NSPLIT][TT*HH];  // partials of h@U
__device__ float g_sp[NSPLIT][TT*HH];  // partials of z@W
__device__ float g_Sp[NSPLIT][TT*TT];  // partials of z@u^T
__device__ float g_R1p[2][TT*HH];      // partials of S@d
__device__ float g_R2p[2][TT*HH];      // partials of S@(d.*P)
__device__ float g_z [TT*HH];
__device__ float g_u [TT*HH];          // h .* z
__device__ float g_s [TT*HH];          // z@W + b (finalized by k_grad)
__device__ float g_d [TT*HH];
__device__ float g_P [TT*HH];          // column-wise inclusive cumsum of h
__device__ float g_c [TT];             // row sums of h

// =====================================================================
// 32x32 tile partial GEMM (NN), K-chunk of 128, double-buffered, 2x2 micro
// =====================================================================
__device__ __forceinline__ void gemm_nn_part(
    const float* __restrict__ A, const float* __restrict__ B,
    float* __restrict__ Cp, int N, int K,
    int row0, int col0, int kbase)
{
    __shared__ __align__(16) float Ast[2][32][34];
    __shared__ __align__(16) float Bs [2][32][34];
    const int tid = threadIdx.x;
    const int tx = tid & 15, ty = tid >> 4;
    const int r_ld = tid >> 5, c_ld = tid & 31;

    #pragma unroll
    for (int i = 0; i < 4; i++) {
        int r = r_ld + i * 8;
        Ast[0][c_ld][r] = A[(row0 + r) * K + kbase + c_ld];
        Bs [0][r][c_ld] = B[(kbase + r) * N + col0 + c_ld];
    }
    __syncthreads();

    float acc00=0.f, acc01=0.f, acc10=0.f, acc11=0.f;
    float a_reg[4], b_reg[4];
    const int NT = KSPL / 32;  // 4

    #pragma unroll
    for (int t = 0; t < NT; t++) {
        const int buf = t & 1;
        if (t + 1 < NT) {
            const int k0 = kbase + (t + 1) * 32;
            #pragma unroll
            for (int i = 0; i < 4; i++) {
                int r = r_ld + i * 8;
                a_reg[i] = A[(row0 + r) * K + k0 + c_ld];
                b_reg[i] = B[(k0 + r) * N + col0 + c_ld];
            }
        }
        #pragma unroll
        for (int kk = 0; kk < 32; kk++) {
            float2 av = *(const float2*)&Ast[buf][kk][2 * ty];
            float2 bv = *(const float2*)&Bs [buf][kk][2 * tx];
            acc00 += av.x * bv.x; acc01 += av.x * bv.y;
            acc10 += av.y * bv.x; acc11 += av.y * bv.y;
        }
        if (t + 1 < NT) {
            #pragma unroll
            for (int i = 0; i < 4; i++) {
                int r = r_ld + i * 8;
                Ast[buf ^ 1][c_ld][r] = a_reg[i];
                Bs [buf ^ 1][r][c_ld] = b_reg[i];
            }
        }
        __syncthreads();
    }

    const int rr0 = row0 + 2 * ty, cc0 = col0 + 2 * tx;
    *(float2*)&Cp[ rr0      * N + cc0] = make_float2(acc00, acc01);
    *(float2*)&Cp[(rr0 + 1) * N + cc0] = make_float2(acc10, acc11);
}

// =====================================================================
// 32x32 tile partial GEMM (NT): Cp[t,i] += sum_k A[t,k]*B[i,k]
// =====================================================================
__device__ __forceinline__ void gemm_nt_part(
    const float* __restrict__ A, const float* __restrict__ B,
    float* __restrict__ Cp,
    int row0, int col0, int kbase)
{
    __shared__ __align__(16) float Ast[2][32][34];
    __shared__ __align__(16) float Bs [2][32][34];
    const int tid = threadIdx.x;
    const int tx = tid & 15, ty = tid >> 4;
    const int r_ld = tid >> 5, c_ld = tid & 31;

    #pragma unroll
    for (int i = 0; i < 4; i++) {
        int r = r_ld + i * 8;
        Ast[0][c_ld][r] = A[(row0 + r) * HH + kbase + c_ld];
        Bs [0][c_ld][r] = B[(col0 + r) * HH + kbase + c_ld];
    }
    __syncthreads();

    float acc00=0.f, acc01=0.f, acc10=0.f, acc11=0.f;
    float a_reg[4], b_reg[4];
    const int NT = KSPL / 32;

    #pragma unroll
    for (int t = 0; t < NT; t++) {
        const int buf = t & 1;
        if (t + 1 < NT) {
            const int k0 = kbase + (t + 1) * 32;
            #pragma unroll
            for (int i = 0; i < 4; i++) {
                int r = r_ld + i * 8;
                a_reg[i] = A[(row0 + r) * HH + k0 + c_ld];
                b_reg[i] = B[(col0 + r) * HH + k0 + c_ld];
            }
        }
        #pragma unroll
        for (int kk = 0; kk < 32; kk++) {
            float2 av = *(const float2*)&Ast[buf][kk][2 * ty];
            float2 bv = *(const float2*)&Bs [buf][kk][2 * tx];
            acc00 += av.x * bv.x; acc01 += av.x * bv.y;
            acc10 += av.y * bv.x; acc11 += av.y * bv.y;
        }
        if (t + 1 < NT) {
            #pragma unroll
            for (int i = 0; i < 4; i++) {
                int r = r_ld + i * 8;
                Ast[buf ^ 1][c_ld][r] = a_reg[i];
                Bs [buf ^ 1][c_ld][r] = b_reg[i];
            }
        }
        __syncthreads();
    }

    const int rr0 = row0 + 2 * ty, cc0 = col0 + 2 * tx;
    *(float2*)&Cp[ rr0      * TT + cc0] = make_float2(acc00, acc01);
    *(float2*)&Cp[(rr0 + 1) * TT + cc0] = make_float2(acc10, acc11);
}

// ===== K1: gemm_z partials (512 blocks) + prep (34 blocks) =====
__global__ __launch_bounds__(256) void k1(const float* __restrict__ h,
                                          const float* __restrict__ U) {
    const int bid = blockIdx.x;
    if (bid < 512) {
        const int sp = bid >> 7, t = bid & 127;
        gemm_nn_part(h, U, g_zp[sp], HH, HH, (t >> 4) * 32, (t & 15) * 32, sp * KSPL);
    } else {
        const int b = bid - 512;
        if (b < 2) {
            const int q = b * 256 + threadIdx.x;
            float run = 0.f;
            for (int t = 0; t < TT; t++) {
                int idx = t * HH + q;
                run += h[idx];
                g_P[idx] = run;
            }
        } else {
            const int warp = threadIdx.x >> 5, lane = threadIdx.x & 31;
            const int row = (b - 2) * 8 + warp;
            const float* hr = h + row * HH;
            float v = 0.f;
            #pragma unroll
            for (int j = 0; j < 16; j++) v += hr[lane + j * 32];
            #pragma unroll
            for (int o = 16; o; o >>= 1) v += __shfl_xor_sync(0xffffffffu, v, o);
            if (lane == 0) g_c[row] = v;
        }
    }
}

// ===== K2: z = relu(sum partials + a), u = h.*z  (128 blocks) =====
__global__ __launch_bounds__(256) void k2(const float* __restrict__ h,
                                          const float* __restrict__ a) {
    const int e = (blockIdx.x * 256 + threadIdx.x) * 4;
    const int col = e & (HH - 1);
    float4 p0 = *(const float4*)&g_zp[0][e];
    float4 p1 = *(const float4*)&g_zp[1][e];
    float4 p2 = *(const float4*)&g_zp[2][e];
    float4 p3 = *(const float4*)&g_zp[3][e];
    float4 av = *(const float4*)&a[col];
    float4 hv = *(const float4*)&h[e];
    float4 z;
    z.x = fmaxf(p0.x + p1.x + p2.x + p3.x + av.x, 0.f);
    z.y = fmaxf(p0.y + p1.y + p2.y + p3.y + av.y, 0.f);
    z.z = fmaxf(p0.z + p1.z + p2.z + p3.z + av.z, 0.f);
    z.w = fmaxf(p0.w + p1.w + p2.w + p3.w + av.w, 0.f);
    *(float4*)&g_z[e] = z;
    *(float4*)&g_u[e] = make_float4(hv.x * z.x, hv.y * z.y, hv.z * z.z, hv.w * z.w);
}

// ===== K3: gemm_s partials (512 blocks) + scores partials (256 blocks) =====
__global__ __launch_bounds__(256) void k3(const float* __restrict__ W) {
    const int bid = blockIdx.x;
    if (bid < 512) {
        const int sp = bid >> 7, t = bid & 127;
        gemm_nn_part(g_z, W, g_sp[sp], HH, HH, (t >> 4) * 32, (t & 15) * 32, sp * KSPL);
    } else {
        const int b = bid - 512;
        const int sp = b >> 6, t = b & 63;
        gemm_nt_part(g_z, g_u, g_Sp[sp], (t >> 3) * 32, (t & 7) * 32, sp * KSPL);
    }
}

// ---------------- block reductions ----------------
__device__ __forceinline__ float2 brsum2(float a, float b, float2* sh) {
    #pragma unroll
    for (int o = 16; o; o >>= 1) {
        a += __shfl_xor_sync(0xffffffffu, a, o);
        b += __shfl_xor_sync(0xffffffffu, b, o);
    }
    if ((threadIdx.x & 31) == 0) sh[threadIdx.x >> 5] = make_float2(a, b);
    __syncthreads();
    float sa = 0.f, sb = 0.f;
    #pragma unroll
    for (int i = 0; i < 8; i++) { sa += sh[i].x; sb += sh[i].y; }
    __syncthreads();
    return make_float2(sa, sb);
}
__device__ __forceinline__ float brsum1(float a, float2* sh) {
    #pragma unroll
    for (int o = 16; o; o >>= 1) a += __shfl_xor_sync(0xffffffffu, a, o);
    if ((threadIdx.x & 31) == 0) sh[threadIdx.x >> 5].x = a;
    __syncthreads();
    float s = 0.f;
    #pragma unroll
    for (int i = 0; i < 8; i++) s += sh[i].x;
    __syncthreads();
    return s;
}

// ===== K4: reduce s partials + bias -> g_s; LN/CE backward -> g_d  (256 blocks) =====
__global__ __launch_bounds__(256) void k4(const float* __restrict__ bias,
                                          const float* __restrict__ gamma,
                                          const float* __restrict__ beta,
                                          const int* __restrict__ targets) {
    __shared__ float2 sh[8];
    const int t = blockIdx.x;
    const int tid = threadIdx.x;
    const int i0 = t * HH + tid, i1 = i0 + 256;

    float s0 = g_sp[0][i0] + g_sp[1][i0] + g_sp[2][i0] + g_sp[3][i0] + bias[tid];
    float s1 = g_sp[0][i1] + g_sp[1][i1] + g_sp[2][i1] + g_sp[3][i1] + bias[tid + 256];
    g_s[i0] = s0; g_s[i1] = s1;

    float2 r = brsum2(s0 + s1, s0 * s0 + s1 * s1, sh);
    float mu = r.x * (1.f / HH);
    float var = r.y * (1.f / HH) - mu * mu;
    float sinv = rsqrtf(var + LN_EPS);
    float xh0 = (s0 - mu) * sinv, xh1 = (s1 - mu) * sinv;

    float ga0 = gamma[tid], ga1 = gamma[tid + 256];
    float y0 = xh0 * ga0 + beta[tid];
    float y1 = xh1 * ga1 + beta[tid + 256];

    float p0 = __expf(y0), p1 = __expf(y1);
    float Zs = brsum1(p0 + p1, sh);
    float inv = 1.f / Zs;
    p0 *= inv; p1 *= inv;

    const int tgt = targets[t];
    float gg0 = ga0 * (p0 - (tid == tgt ? 1.f : 0.f));
    float gg1 = ga1 * (p1 - (tid + 256 == tgt ? 1.f : 0.f));

    float2 m2 = brsum2(gg0 + gg1, gg0 * xh0 + gg1 * xh1, sh);
    float mg  = m2.x * (1.f / HH);
    float mgx = m2.y * (1.f / HH);

    g_d[i0] = sinv * (gg0 - mg - xh0 * mgx);
    g_d[i1] = sinv * (gg1 - mg - xh1 * mgx);
}

// ===== K5: dual GEMM, split-K=2, S reduced+masked inline  (256 blocks) =====
__global__ __launch_bounds__(256) void k5() {
    __shared__ __align__(16) float Ast[2][32][34];
    __shared__ __align__(16) float B1s[2][32][34];
    __shared__ __align__(16) float B2s[2][32][34];

    const int bid = blockIdx.x;
    const int sp = bid >> 7, tb = bid & 127;
    const int row0 = (tb >> 4) * 32, col0 = (tb & 15) * 32;
    const int kbase = sp * 128;

    const int tid = threadIdx.x;
    const int tx = tid & 15, ty = tid >> 4;
    const int r_ld = tid >> 5, c_ld = tid & 31;

    // preload tile 0
    #pragma unroll
    for (int i = 0; i < 4; i++) {
        int r = r_ld + i * 8;
        int tt = row0 + r, ii = kbase + c_ld;
        int sidx = tt * TT + ii;
        float v = g_Sp[0][sidx] + g_Sp[1][sidx] + g_Sp[2][sidx] + g_Sp[3][sidx];
        Ast[0][c_ld][r] = (ii < tt) ? (v + g_c[ii]) : 0.f;
        int bidx = (kbase + r) * HH + col0 + c_ld;
        float dv = g_d[bidx];
        B1s[0][r][c_ld] = dv;
        B2s[0][r][c_ld] = dv * g_P[bidx];
    }
    __syncthreads();

    float a00=0.f,a01=0.f,a10=0.f,a11=0.f;
    float b00=0.f,b01=0.f,b10=0.f,b11=0.f;
    float a_reg[4], d_reg[4], q_reg[4];
    const int NT = 4;  // 128 / 32

    #pragma unroll
    for (int t = 0; t < NT; t++) {
        const int buf = t & 1;
        if (t + 1 < NT) {
            const int k0 = kbase + (t + 1) * 32;
            #pragma unroll
            for (int i = 0; i < 4; i++) {
                int r = r_ld + i * 8;
                int tt = row0 + r, ii = k0 + c_ld;
                int sidx = tt * TT + ii;
                float v = g_Sp[0][sidx] + g_Sp[1][sidx] + g_Sp[2][sidx] + g_Sp[3][sidx];
                a_reg[i] = (ii < tt) ? (v + g_c[ii]) : 0.f;
                int bidx = (k0 + r) * HH + col0 + c_ld;
                float dv = g_d[bidx];
                d_reg[i] = dv;
                q_reg[i] = dv * g_P[bidx];
            }
        }
        #pragma unroll
        for (int kk = 0; kk < 32; kk++) {
            float2 sv = *(const float2*)&Ast[buf][kk][2 * ty];
            float2 dv = *(const float2*)&B1s[buf][kk][2 * tx];
            float2 qv = *(const float2*)&B2s[buf][kk][2 * tx];
            a00 += sv.x * dv.x; a01 += sv.x * dv.y;
            a10 += sv.y * dv.x; a11 += sv.y * dv.y;
            b00 += sv.x * qv.x; b01 += sv.x * qv.y;
            b10 += sv.y * qv.x; b11 += sv.y * qv.y;
        }
        if (t + 1 < NT) {
            #pragma unroll
            for (int i = 0; i < 4; i++) {
                int r = r_ld + i * 8;
                Ast[buf ^ 1][c_ld][r] = a_reg[i];
                B1s[buf ^ 1][r][c_ld] = d_reg[i];
                B2s[buf ^ 1][r][c_ld] = q_reg[i];
            }
        }
        __syncthreads();
    }

    const int rr0 = row0 + 2 * ty, cc0 = col0 + 2 * tx;
    *(float2*)&g_R1p[sp][ rr0      * HH + cc0] = make_float2(a00, a01);
    *(float2*)&g_R1p[sp][(rr0 + 1) * HH + cc0] = make_float2(a10, a11);
    *(float2*)&g_R2p[sp][ rr0      * HH + cc0] = make_float2(b00, b01);
    *(float2*)&g_R2p[sp][(rr0 + 1) * HH + cc0] = make_float2(b10, b11);
}

// ===== K6: pre = s - (P*(R1) - R2); out = LN(pre)  (256 blocks) =====
__global__ __launch_bounds__(256) void k6(const float* __restrict__ gamma,
                                          const float* __restrict__ beta,
                                          float* __restrict__ out) {
    __shared__ float2 sh[8];
    const int t = blockIdx.x;
    const int tid = threadIdx.x;
    const int i0 = t * HH + tid, i1 = i0 + 256;

    float r1a = g_R1p[0][i0] + g_R1p[1][i0];
    float r1b = g_R1p[0][i1] + g_R1p[1][i1];
    float r2a = g_R2p[0][i0] + g_R2p[1][i0];
    float r2b = g_R2p[0][i1] + g_R2p[1][i1];

    float pre0 = g_s[i0] - (g_P[i0] * r1a - r2a);
    float pre1 = g_s[i1] - (g_P[i1] * r1b - r2b);

    float2 r = brsum2(pre0 + pre1, pre0 * pre0 + pre1 * pre1, sh);
    float mu = r.x * (1.f / HH);
    float var = r.y * (1.f / HH) - mu * mu;
    float sinv = rsqrtf(var + LN_EPS);

    out[i0] = (pre0 - mu) * sinv * gamma[tid]       + beta[tid];
    out[i1] = (pre1 - mu) * sinv * gamma[tid + 256] + beta[tid + 256];
}

// ---------------- launch ----------------
extern "C" void kernel_launch(void* const* d_in, const int* in_sizes, int n_in,
                              void* d_out, int out_size) {
    const float* h      = (const float*)d_in[0];
    const float* U      = (const float*)d_in[1];
    const float* W      = (const float*)d_in[2];
    const float* a      = (const float*)d_in[3];
    const float* b      = (const float*)d_in[4];
    const float* gamma  = (const float*)d_in[5];
    const float* beta   = (const float*)d_in[6];
    const int*   tgt    = (const int*)  d_in[7];
    float*       out    = (float*)d_out;

    dim3 blk(256);
    k1<<<546, blk>>>(h, U);                 // z partials + P + c
    k2<<<128, blk>>>(h, a);                 // z = relu(.), u = h.*z
    k3<<<768, blk>>>(W);                    // s partials + S partials
    k4<<<256, blk>>>(b, gamma, beta, tgt);  // g_s finalize + g_d
    k5<<<256, blk>>>();                     // R1/R2 partials (S inline)
    k6<<<256, blk>>>(gamma, beta, out);     // final LN -> out
}